// round 4
// baseline (speedup 1.0000x reference)
#include <cuda_runtime.h>
#include <cuda_fp16.h>
#include <math.h>
#include <stdint.h>

// ---------------------------------------------------------------------------
// SpatioTemporalPerformerEncoder — R4: fp16 mma.sync m16n8k16 + ldmatrix
// B=2, T=8, L=512 -> 8192 rows, D=512, H=8, dh=64, m=256, FF=2048, depth=4
// ---------------------------------------------------------------------------

#define Bc     2
#define Hc     8
#define Nc     4096
#define Dc     512
#define DHc    64
#define Mc     256
#define FFc    2048
#define DEPTHc 4
#define ROWSc  8192
#define BHc    16
#define QKVW   1536

#define DN_CONST    0.35355339059327373f
#define DIAG_SCALE  0.0625f
#define RATIO_CONST 0.0625f
#define EPSK        1e-4f
#define LNEPS       1e-5f

// ------------------------- scratch (device globals) ------------------------
__device__ float g_ln   [(size_t)ROWSc * Dc];
__device__ float g_qkv  [(size_t)ROWSc * QKVW];
__device__ float g_qp   [(size_t)BHc * Nc * Mc];
__device__ float g_kp   [(size_t)BHc * Nc * Mc];
__device__ float g_ff   [(size_t)ROWSc * FFc];
__device__ float g_ctx  [BHc * Mc * DHc];
__device__ float g_ksum [BHc * Mc];
__device__ float g_qdiag[BHc * Nc];
__device__ float g_kdiag[BHc * Nc];
__device__ float g_bmax [BHc * Nc];
__device__ float g_hmax [BHc];
__device__ float g_dinv [BHc * Nc];
// transposed weights [N][K]
__device__ float g_wqkvT[(size_t)DEPTHc * QKVW * Dc];
__device__ float g_woT  [(size_t)DEPTHc * Dc * Dc];
__device__ float g_wff1T[(size_t)DEPTHc * FFc * Dc];
__device__ float g_wff2T[(size_t)DEPTHc * Dc * FFc];

// ------------------------------ helpers ------------------------------------
__device__ __forceinline__ uint32_t smem_to_u32(const void* p) {
    uint32_t a;
    asm("{ .reg .u64 t; cvta.to.shared.u64 t, %1; cvt.u32.u64 %0, t; }"
        : "=r"(a) : "l"(p));
    return a;
}

__device__ __forceinline__ uint32_t f2h2(float a, float b) {
    __half2 h = __floats2half2_rn(a, b);
    return *(uint32_t*)&h;
}

__device__ __forceinline__ void ldsm4(uint32_t& r0, uint32_t& r1, uint32_t& r2,
                                      uint32_t& r3, uint32_t a) {
    asm volatile("ldmatrix.sync.aligned.m8n8.x4.shared.b16 {%0,%1,%2,%3}, [%4];"
                 : "=r"(r0), "=r"(r1), "=r"(r2), "=r"(r3) : "r"(a));
}
__device__ __forceinline__ void ldsm2(uint32_t& r0, uint32_t& r1, uint32_t a) {
    asm volatile("ldmatrix.sync.aligned.m8n8.x2.shared.b16 {%0,%1}, [%2];"
                 : "=r"(r0), "=r"(r1) : "r"(a));
}
__device__ __forceinline__ void mma_f16(float c[4], const uint32_t a[4],
                                        const uint32_t b[2]) {
    asm volatile(
        "mma.sync.aligned.m16n8k16.row.col.f32.f16.f16.f32 "
        "{%0,%1,%2,%3}, {%4,%5,%6,%7}, {%8,%9}, {%0,%1,%2,%3};"
        : "+f"(c[0]), "+f"(c[1]), "+f"(c[2]), "+f"(c[3])
        : "r"(a[0]), "r"(a[1]), "r"(a[2]), "r"(a[3]), "r"(b[0]), "r"(b[1]));
}

// ------------------------- fp16 tensor-core GEMM ---------------------------
// C = scale*(A[M,K] @ B[N,K]^T) (+bias)(+gelu|+residual)
// BM=BN=128, BK=32, 256 threads (8 warps 2x4), warp tile 64x32.
// smem rows padded to 40 halves (80B pitch -> conflict-free ldmatrix/STS).
#define EPI_NONE 0
#define EPI_GELU 1
#define EPI_ADD  2

template <int EPI, bool BH>
__global__ __launch_bounds__(256)
void hgemm(const float* __restrict__ A, int lda,
           const float* __restrict__ Bm, int ldb,
           const float* __restrict__ bias, const float* __restrict__ R,
           float* __restrict__ C, int ldc, int K, float scale) {
    __shared__ __align__(16) uint16_t sA[2][128 * 40];
    __shared__ __align__(16) uint16_t sB[2][128 * 40];

    if (BH) {
        int z = blockIdx.z;
        int b = z >> 3, h = z & 7;
        A += (size_t)b * Nc * lda + (size_t)h * DHc;
        C += (size_t)z * Nc * ldc;
    }
    int m0 = blockIdx.y * 128, n0 = blockIdx.x * 128;
    int tid = threadIdx.x, lane = tid & 31, warp = tid >> 5;
    int wm = warp >> 2, wn = warp & 3;

    // copy-in: 2 threads per row (16 cols each), 128 rows
    int crow = tid & 127, ccg = tid >> 7;
    const float* Ap = A + (size_t)(m0 + crow) * lda + ccg * 16;
    const float* Bp = Bm + (size_t)(n0 + crow) * ldb + ccg * 16;
    uint32_t sdst = (uint32_t)crow * 40 + ccg * 16;   // in halves

    uint32_t aBase = smem_to_u32(sA), bBase = smem_to_u32(sB);
    uint32_t aOff = (((lane & 15) * 40) + (lane >> 4) * 8) * 2;
    uint32_t bOff = (((lane & 7) * 40) + ((lane >> 3) & 1) * 8) * 2;

    float c[4][4][4];
#pragma unroll
    for (int i = 0; i < 4; i++)
#pragma unroll
        for (int j = 0; j < 4; j++)
#pragma unroll
            for (int l = 0; l < 4; l++) c[i][j][l] = 0.0f;

    uint32_t ua[8], ub[8];
#define PREF(t)                                                               \
    {                                                                         \
        int k0 = (t) * 32;                                                    \
        _Pragma("unroll")                                                     \
        for (int i = 0; i < 4; i++) {                                         \
            float4 va = *(const float4*)(Ap + k0 + i * 4);                    \
            float4 vb = *(const float4*)(Bp + k0 + i * 4);                    \
            ua[2 * i] = f2h2(va.x, va.y); ua[2 * i + 1] = f2h2(va.z, va.w);   \
            ub[2 * i] = f2h2(vb.x, vb.y); ub[2 * i + 1] = f2h2(vb.z, vb.w);   \
        }                                                                     \
    }
#define STORE(buf)                                                            \
    {                                                                         \
        *(uint4*)&sA[buf][sdst]     = make_uint4(ua[0], ua[1], ua[2], ua[3]); \
        *(uint4*)&sA[buf][sdst + 8] = make_uint4(ua[4], ua[5], ua[6], ua[7]); \
        *(uint4*)&sB[buf][sdst]     = make_uint4(ub[0], ub[1], ub[2], ub[3]); \
        *(uint4*)&sB[buf][sdst + 8] = make_uint4(ub[4], ub[5], ub[6], ub[7]); \
    }

    int T = K >> 5;
    PREF(0)
    STORE(0)
    __syncthreads();

    for (int t = 0; t < T; t++) {
        if (t + 1 < T) PREF(t + 1)
        int buf = t & 1;
        uint32_t aTile = aBase + buf * 10240;
        uint32_t bTile = bBase + buf * 10240;
#pragma unroll
        for (int k16 = 0; k16 < 32; k16 += 16) {
            uint32_t af[4][4], bf[4][2];
#pragma unroll
            for (int mi = 0; mi < 4; mi++)
                ldsm4(af[mi][0], af[mi][1], af[mi][2], af[mi][3],
                      aTile + ((wm * 64 + mi * 16) * 40 + k16) * 2 + aOff);
#pragma unroll
            for (int ni = 0; ni < 4; ni++)
                ldsm2(bf[ni][0], bf[ni][1],
                      bTile + ((wn * 32 + ni * 8) * 40 + k16) * 2 + bOff);
#pragma unroll
            for (int mi = 0; mi < 4; mi++)
#pragma unroll
                for (int ni = 0; ni < 4; ni++)
                    mma_f16(c[mi][ni], af[mi], bf[ni]);
        }
        if (t + 1 < T) STORE((t + 1) & 1)
        __syncthreads();
    }
#undef PREF
#undef STORE

    // epilogue
    int g = lane >> 2, tig = lane & 3;
#pragma unroll
    for (int mi = 0; mi < 4; mi++) {
#pragma unroll
        for (int ni = 0; ni < 4; ni++) {
            int row = m0 + wm * 64 + mi * 16 + g;
            int col = n0 + wn * 32 + ni * 8 + 2 * tig;
#pragma unroll
            for (int half = 0; half < 2; half++) {
                int r = row + half * 8;
                float v0 = c[mi][ni][half * 2 + 0] * scale;
                float v1 = c[mi][ni][half * 2 + 1] * scale;
                if (bias) { v0 += bias[col]; v1 += bias[col + 1]; }
                if (EPI == EPI_GELU) {
                    v0 = 0.5f * v0 * (1.0f + erff(v0 * 0.70710678118654752f));
                    v1 = 0.5f * v1 * (1.0f + erff(v1 * 0.70710678118654752f));
                }
                if (EPI == EPI_ADD) {
                    v0 += R[(size_t)r * ldc + col];
                    v1 += R[(size_t)r * ldc + col + 1];
                }
                float2 o = {v0, v1};
                *(float2*)&C[(size_t)r * ldc + col] = o;
            }
        }
    }
}

// ----------------------- batched weight transpose --------------------------
__global__ __launch_bounds__(256)
void transpose_all(const float* __restrict__ Wqkv, const float* __restrict__ Wo,
                   const float* __restrict__ Wff1, const float* __restrict__ Wff2,
                   float* __restrict__ qkvT, float* __restrict__ woT,
                   float* __restrict__ ff1T, float* __restrict__ ff2T) {
    __shared__ float tbuf[32][33];
    int z = blockIdx.z;
    int type = z & 3, l = z >> 2;
    int K, N;
    const float* in;
    float* out;
    if (type == 0)      { K = Dc;  N = QKVW; in = Wqkv + (size_t)l * Dc * QKVW; out = qkvT + (size_t)l * QKVW * Dc; }
    else if (type == 1) { K = Dc;  N = Dc;   in = Wo   + (size_t)l * Dc * Dc;   out = woT  + (size_t)l * Dc * Dc; }
    else if (type == 2) { K = Dc;  N = FFc;  in = Wff1 + (size_t)l * Dc * FFc;  out = ff1T + (size_t)l * FFc * Dc; }
    else                { K = FFc; N = Dc;   in = Wff2 + (size_t)l * FFc * Dc;  out = ff2T + (size_t)l * Dc * FFc; }

    int nx = blockIdx.x * 32, kx = blockIdx.y * 32;
    if (nx >= N || kx >= K) return;
    int tx = threadIdx.x & 31, ty = threadIdx.x >> 5;
#pragma unroll
    for (int i = 0; i < 4; i++)
        tbuf[ty + i * 8][tx] = in[(size_t)(kx + ty + i * 8) * N + nx + tx];
    __syncthreads();
#pragma unroll
    for (int i = 0; i < 4; i++)
        out[(size_t)(nx + ty + i * 8) * K + kx + tx] = tbuf[tx][ty + i * 8];
}

// ------------------------------ copy x -> h --------------------------------
__global__ void copy_kernel(const float* __restrict__ x, float* __restrict__ h) {
    size_t i = (size_t)blockIdx.x * 256 + threadIdx.x;
    h[i] = x[i];
}

// ------------------------------- layernorm ---------------------------------
__global__ __launch_bounds__(256)
void ln_kernel(const float* __restrict__ x, const float* __restrict__ g,
               const float* __restrict__ b, float* __restrict__ out) {
    int row = blockIdx.x;
    int t = threadIdx.x;
    const float* xr = x + (size_t)row * Dc;
    float v0 = xr[t], v1 = xr[t + 256];

    __shared__ float red[256];
    red[t] = v0 + v1;
    __syncthreads();
#pragma unroll
    for (int o = 128; o > 0; o >>= 1) {
        if (t < o) red[t] += red[t + o];
        __syncthreads();
    }
    float mu = red[0] * (1.0f / Dc);
    __syncthreads();

    float d0 = v0 - mu, d1 = v1 - mu;
    red[t] = d0 * d0 + d1 * d1;
    __syncthreads();
#pragma unroll
    for (int o = 128; o > 0; o >>= 1) {
        if (t < o) red[t] += red[t + o];
        __syncthreads();
    }
    float rs = rsqrtf(red[0] * (1.0f / Dc) + LNEPS);

    float* orow = out + (size_t)row * Dc;
    orow[t]       = d0 * rs * g[t]       + b[t];
    orow[t + 256] = d1 * rs * g[t + 256] + b[t + 256];
}

// ------------------- diag: per-(bh,row) 0.5*dn^2*|q|^2, |k|^2 --------------
__global__ __launch_bounds__(256)
void diag_kernel(const float* __restrict__ qkv, float* __restrict__ qdiag,
                 float* __restrict__ kdiag) {
    int row = blockIdx.x;
    int w = threadIdx.x >> 5, lane = threadIdx.x & 31;
    const float* base = qkv + (size_t)row * QKVW + w * DHc;
    float q0 = base[lane], q1 = base[lane + 32];
    float k0 = base[Dc + lane], k1 = base[Dc + lane + 32];
    float sq = q0 * q0 + q1 * q1;
    float sk = k0 * k0 + k1 * k1;
#pragma unroll
    for (int o = 16; o > 0; o >>= 1) {
        sq += __shfl_down_sync(0xffffffffu, sq, o);
        sk += __shfl_down_sync(0xffffffffu, sk, o);
    }
    if (lane == 0) {
        int bh = (row >> 12) * Hc + w;
        int n = row & (Nc - 1);
        qdiag[(size_t)bh * Nc + n] = sq * DIAG_SCALE;
        kdiag[(size_t)bh * Nc + n] = sk * DIAG_SCALE;
    }
}

// ---------------- q features: per-row max + exp (in place) -----------------
__global__ __launch_bounds__(256)
void featq_finish(float* __restrict__ qp, const float* __restrict__ qdiag) {
    int w = threadIdx.x >> 5, lane = threadIdx.x & 31;
    int rr = blockIdx.x * 8 + w;
    float* p = qp + (size_t)rr * Mc + lane * 8;
    float4 v0 = *(float4*)p;
    float4 v1 = *(float4*)(p + 4);
    float mx = fmaxf(fmaxf(fmaxf(v0.x, v0.y), fmaxf(v0.z, v0.w)),
                     fmaxf(fmaxf(v1.x, v1.y), fmaxf(v1.z, v1.w)));
#pragma unroll
    for (int o = 16; o > 0; o >>= 1)
        mx = fmaxf(mx, __shfl_xor_sync(0xffffffffu, mx, o));
    float sub = qdiag[rr] + mx;
    v0.x = RATIO_CONST * (expf(v0.x - sub) + EPSK);
    v0.y = RATIO_CONST * (expf(v0.y - sub) + EPSK);
    v0.z = RATIO_CONST * (expf(v0.z - sub) + EPSK);
    v0.w = RATIO_CONST * (expf(v0.w - sub) + EPSK);
    v1.x = RATIO_CONST * (expf(v1.x - sub) + EPSK);
    v1.y = RATIO_CONST * (expf(v1.y - sub) + EPSK);
    v1.z = RATIO_CONST * (expf(v1.z - sub) + EPSK);
    v1.w = RATIO_CONST * (expf(v1.w - sub) + EPSK);
    *(float4*)p = v0;
    *(float4*)(p + 4) = v1;
}

// ---------------- k features pass A: per-row max ---------------------------
__global__ __launch_bounds__(256)
void featk_rowmax(const float* __restrict__ kp, float* __restrict__ bmax) {
    int w = threadIdx.x >> 5, lane = threadIdx.x & 31;
    int rr = blockIdx.x * 8 + w;
    const float* p = kp + (size_t)rr * Mc + lane * 8;
    float4 v0 = *(const float4*)p;
    float4 v1 = *(const float4*)(p + 4);
    float mx = fmaxf(fmaxf(fmaxf(v0.x, v0.y), fmaxf(v0.z, v0.w)),
                     fmaxf(fmaxf(v1.x, v1.y), fmaxf(v1.z, v1.w)));
#pragma unroll
    for (int o = 16; o > 0; o >>= 1)
        mx = fmaxf(mx, __shfl_xor_sync(0xffffffffu, mx, o));
    if (lane == 0) bmax[rr] = mx;
}

// ------------------------- per-head global max -----------------------------
__global__ __launch_bounds__(256)
void hmax_kernel(const float* __restrict__ bmax, float* __restrict__ hmax) {
    int bh = blockIdx.x;
    int t = threadIdx.x;
    float m = -1e30f;
    for (int i = t; i < Nc; i += 256) m = fmaxf(m, bmax[(size_t)bh * Nc + i]);
#pragma unroll
    for (int o = 16; o > 0; o >>= 1) m = fmaxf(m, __shfl_xor_sync(0xffffffffu, m, o));
    __shared__ float w[8];
    if ((t & 31) == 0) w[t >> 5] = m;
    __syncthreads();
    if (t == 0) {
        float mm = w[0];
#pragma unroll
        for (int i = 1; i < 8; i++) mm = fmaxf(mm, w[i]);
        hmax[bh] = mm;
    }
}

// ---------------- k features pass B: exp (in place) ------------------------
__global__ __launch_bounds__(256)
void featk2_kernel(float* __restrict__ kp, const float* __restrict__ kdiag,
                   const float* __restrict__ hmax) {
    size_t i4 = (size_t)blockIdx.x * 256 + threadIdx.x;
    size_t idx = i4 * 4;
    int bh = (int)(idx >> 20);
    int n  = (int)((idx >> 8) & (Nc - 1));
    float sub = kdiag[(size_t)bh * Nc + n] + hmax[bh];
    float4 v = *(float4*)&kp[idx];
    v.x = RATIO_CONST * (expf(v.x - sub) + EPSK);
    v.y = RATIO_CONST * (expf(v.y - sub) + EPSK);
    v.z = RATIO_CONST * (expf(v.z - sub) + EPSK);
    v.w = RATIO_CONST * (expf(v.w - sub) + EPSK);
    *(float4*)&kp[idx] = v;
}

// ---------------------------- zero ctx / ksum ------------------------------
__global__ void zero_kernel(float* __restrict__ ctx, float* __restrict__ ksum) {
    int i = blockIdx.x * 256 + threadIdx.x;
    if (i < BHc * Mc * DHc) ctx[i] = 0.0f;
    if (i < BHc * Mc) ksum[i] = 0.0f;
}

// --------------------------------- k_sum -----------------------------------
__global__ __launch_bounds__(256)
void ksum_kernel(const float* __restrict__ kp, float* __restrict__ ksum) {
    int bh = blockIdx.x;
    int n0 = blockIdx.y * (Nc / 8);
    int t = threadIdx.x;
    float s = 0.0f;
    const float* base = kp + ((size_t)bh * Nc + n0) * Mc + t;
    for (int n = 0; n < Nc / 8; n++) s += base[(size_t)n * Mc];
    atomicAdd(&ksum[bh * Mc + t], s);
}

// ------------------------------- ctx = kp^T v ------------------------------
__global__ __launch_bounds__(256)
void ctx_kernel(const float* __restrict__ kp, const float* __restrict__ qkv,
                float* __restrict__ ctx) {
    int bh = blockIdx.x;
    int split = blockIdx.y;
    int b = bh >> 3, h = bh & 7;
    const int NS = Nc / 16;
    int n0 = split * NS;
    int t = threadIdx.x;
    int tx = t & 63;
    int ty = t >> 6;

    __shared__ float kps[32][256];
    __shared__ float vs[32][64];

    float acc[4][16];
#pragma unroll
    for (int i = 0; i < 4; i++)
#pragma unroll
        for (int j = 0; j < 16; j++) acc[i][j] = 0.0f;

    for (int nc = 0; nc < NS; nc += 32) {
#pragma unroll
        for (int i = 0; i < 8; i++) {
            int li = t + i * 256;
            int r = li >> 6;
            int cc = (li & 63) * 4;
            *(float4*)&kps[r][cc] =
                *(const float4*)&kp[((size_t)bh * Nc + n0 + nc + r) * Mc + cc];
        }
#pragma unroll
        for (int i = 0; i < 2; i++) {
            int li = t + i * 256;
            int r = li >> 4;
            int cc = (li & 15) * 4;
            *(float4*)&vs[r][cc] =
                *(const float4*)&qkv[((size_t)(b * Nc + n0 + nc + r)) * QKVW +
                                     2 * Dc + h * DHc + cc];
        }
        __syncthreads();

#pragma unroll 4
        for (int nn = 0; nn < 32; nn++) {
            float kv[4];
#pragma unroll
            for (int mm = 0; mm < 4; mm++) kv[mm] = kps[nn][tx + mm * 64];
            float vv[16];
            *(float4*)&vv[0]  = *(float4*)&vs[nn][ty * 16];
            *(float4*)&vv[4]  = *(float4*)&vs[nn][ty * 16 + 4];
            *(float4*)&vv[8]  = *(float4*)&vs[nn][ty * 16 + 8];
            *(float4*)&vv[12] = *(float4*)&vs[nn][ty * 16 + 12];
#pragma unroll
            for (int mm = 0; mm < 4; mm++)
#pragma unroll
                for (int dd = 0; dd < 16; dd++)
                    acc[mm][dd] = fmaf(kv[mm], vv[dd], acc[mm][dd]);
        }
        __syncthreads();
    }

#pragma unroll
    for (int mm = 0; mm < 4; mm++)
#pragma unroll
        for (int dd = 0; dd < 16; dd++)
            atomicAdd(&ctx[((size_t)bh * Mc + tx + mm * 64) * DHc + ty * 16 + dd],
                      acc[mm][dd]);
}

// ------------------------------- d_inv -------------------------------------
__global__ __launch_bounds__(256)
void dinv_kernel(const float* __restrict__ qp, const float* __restrict__ ksum,
                 float* __restrict__ dinv) {
    int w = threadIdx.x >> 5, lane = threadIdx.x & 31;
    int rr = blockIdx.x * 8 + w;
    int bh = rr >> 12;
    float s = 0.0f;
#pragma unroll
    for (int j = 0; j < 8; j++) {
        int m = lane + j * 32;
        s += qp[(size_t)rr * Mc + m] * ksum[bh * Mc + m];
    }
#pragma unroll
    for (int o = 16; o > 0; o >>= 1) s += __shfl_down_sync(0xffffffffu, s, o);
    if (lane == 0) dinv[rr] = 1.0f / s;
}

// ---------------------- out = dinv * (qp @ ctx), merge heads ---------------
__global__ __launch_bounds__(256)
void attnout_kernel(const float* __restrict__ qp, const float* __restrict__ ctx,
                    const float* __restrict__ dinv, float* __restrict__ out) {
    int bh = blockIdx.y;
    int n0 = blockIdx.x * 64;
    int b = bh >> 3, h = bh & 7;
    int t = threadIdx.x;
    int tx = t & 15, ty = t >> 4;

    __shared__ float qs[64][36];
    __shared__ float cs[32][64];

    float acc[4][4];
#pragma unroll
    for (int i = 0; i < 4; i++)
#pragma unroll
        for (int j = 0; j < 4; j++) acc[i][j] = 0.0f;

    for (int k0 = 0; k0 < Mc; k0 += 32) {
#pragma unroll
        for (int i = 0; i < 2; i++) {
            int l = t + i * 256;
            int r = l >> 3;
            int cc = (l & 7) * 4;
            *(float4*)&qs[r][cc] =
                *(const float4*)&qp[((size_t)bh * Nc + n0 + r) * Mc + k0 + cc];
        }
#pragma unroll
        for (int i = 0; i < 2; i++) {
            int l = t + i * 256;
            int r = l >> 4;
            int cc = (l & 15) * 4;
            *(float4*)&cs[r][cc] =
                *(const float4*)&ctx[((size_t)bh * Mc + k0 + r) * DHc + cc];
        }
        __syncthreads();

#pragma unroll
        for (int k = 0; k < 32; k++) {
            float a[4];
#pragma unroll
            for (int i = 0; i < 4; i++) a[i] = qs[ty * 4 + i][k];
            float bb[4];
            *(float4*)bb = *(float4*)&cs[k][tx * 4];
#pragma unroll
            for (int i = 0; i < 4; i++)
#pragma unroll
                for (int j = 0; j < 4; j++)
                    acc[i][j] = fmaf(a[i], bb[j], acc[i][j]);
        }
        __syncthreads();
    }

#pragma unroll
    for (int i = 0; i < 4; i++) {
        int n = n0 + ty * 4 + i;
        float di = dinv[(size_t)bh * Nc + n];
#pragma unroll
        for (int j = 0; j < 4; j++)
            out[((size_t)(b * Nc + n)) * Dc + h * DHc + tx * 4 + j] = acc[i][j] * di;
    }
}

// ------------------------------- launch ------------------------------------
extern "C" void kernel_launch(void* const* d_in, const int* in_sizes, int n_in,
                              void* d_out, int out_size) {
    (void)in_sizes; (void)n_in; (void)out_size;
    const float* x    = (const float*)d_in[0];
    const float* proj = (const float*)d_in[1];
    const float* ln1g = (const float*)d_in[2];
    const float* ln1b = (const float*)d_in[3];
    const float* Wqkv = (const float*)d_in[4];
    const float* bqkv = (const float*)d_in[5];
    const float* Wo   = (const float*)d_in[6];
    const float* bo   = (const float*)d_in[7];
    const float* ln2g = (const float*)d_in[8];
    const float* ln2b = (const float*)d_in[9];
    const float* Wff1 = (const float*)d_in[10];
    const float* bff1 = (const float*)d_in[11];
    const float* Wff2 = (const float*)d_in[12];
    const float* bff2 = (const float*)d_in[13];
    float* h = (float*)d_out;

    static float *p_ln = 0, *p_qkv = 0, *p_qp = 0, *p_kp = 0, *p_ff = 0,
                 *p_ctx = 0, *p_ksum = 0, *p_qdiag = 0, *p_kdiag = 0,
                 *p_bmax = 0, *p_hmax = 0, *p_dinv = 0,
                 *p_wqkvT = 0, *p_woT = 0, *p_wff1T = 0, *p_wff2T = 0;
    if (!p_ln) {
        cudaGetSymbolAddress((void**)&p_ln, g_ln);
        cudaGetSymbolAddress((void**)&p_qkv, g_qkv);
        cudaGetSymbolAddress((void**)&p_qp, g_qp);
        cudaGetSymbolAddress((void**)&p_kp, g_kp);
        cudaGetSymbolAddress((void**)&p_ff, g_ff);
        cudaGetSymbolAddress((void**)&p_ctx, g_ctx);
        cudaGetSymbolAddress((void**)&p_ksum, g_ksum);
        cudaGetSymbolAddress((void**)&p_qdiag, g_qdiag);
        cudaGetSymbolAddress((void**)&p_kdiag, g_kdiag);
        cudaGetSymbolAddress((void**)&p_bmax, g_bmax);
        cudaGetSymbolAddress((void**)&p_hmax, g_hmax);
        cudaGetSymbolAddress((void**)&p_dinv, g_dinv);
        cudaGetSymbolAddress((void**)&p_wqkvT, g_wqkvT);
        cudaGetSymbolAddress((void**)&p_woT, g_woT);
        cudaGetSymbolAddress((void**)&p_wff1T, g_wff1T);
        cudaGetSymbolAddress((void**)&p_wff2T, g_wff2T);
    }

    // launch 0: weight transposes
    transpose_all<<<dim3(64, 64, 16), 256>>>(Wqkv, Wo, Wff1, Wff2,
                                             p_wqkvT, p_woT, p_wff1T, p_wff2T);
    // launch 1
    copy_kernel<<<(ROWSc * Dc) / 256, 256>>>(x, h);

    for (int l = 0; l < DEPTHc; l++) {
        const float* pj = proj + (size_t)l * Mc * DHc;

        ln_kernel<<<ROWSc, 256>>>(h, ln1g + l * Dc, ln1b + l * Dc, p_ln);  // 2

        // launch 3 (profiled): QKV = ln @ WqkvT^T
        hgemm<EPI_NONE, false><<<dim3(QKVW / 128, ROWSc / 128), 256>>>(
            p_ln, Dc, p_wqkvT + (size_t)l * QKVW * Dc, Dc,
            bqkv + l * QKVW, (const float*)0, p_qkv, QKVW, Dc, 1.0f);

        zero_kernel<<<(BHc * Mc * DHc + 255) / 256, 256>>>(p_ctx, p_ksum);

        // dd_q / dd_k: batched [4096x64] @ proj[256x64]^T
        hgemm<EPI_NONE, true><<<dim3(Mc / 128, Nc / 128, BHc), 256>>>(
            p_qkv, QKVW, pj, DHc, (const float*)0, (const float*)0,
            p_qp, Mc, DHc, DN_CONST);
        hgemm<EPI_NONE, true><<<dim3(Mc / 128, Nc / 128, BHc), 256>>>(
            p_qkv + Dc, QKVW, pj, DHc, (const float*)0, (const float*)0,
            p_kp, Mc, DHc, DN_CONST);

        diag_kernel<<<ROWSc, 256>>>(p_qkv, p_qdiag, p_kdiag);
        featq_finish<<<(BHc * Nc) / 8, 256>>>(p_qp, p_qdiag);
        featk_rowmax<<<(BHc * Nc) / 8, 256>>>(p_kp, p_bmax);
        hmax_kernel<<<BHc, 256>>>(p_bmax, p_hmax);
        featk2_kernel<<<(BHc * Nc * Mc / 4) / 256, 256>>>(p_kp, p_kdiag, p_hmax);

        ksum_kernel<<<dim3(BHc, 8), 256>>>(p_kp, p_ksum);
        ctx_kernel<<<dim3(BHc, 16), 256>>>(p_kp, p_qkv, p_ctx);
        dinv_kernel<<<(BHc * Nc) / 8, 256>>>(p_qp, p_ksum, p_dinv);
        attnout_kernel<<<dim3(Nc / 64, BHc), 256>>>(p_qp, p_ctx, p_dinv, p_ln);

        // Wo + residual
        hgemm<EPI_ADD, false><<<dim3(Dc / 128, ROWSc / 128), 256>>>(
            p_ln, Dc, p_woT + (size_t)l * Dc * Dc, Dc,
            bo + l * Dc, h, h, Dc, Dc, 1.0f);

        ln_kernel<<<ROWSc, 256>>>(h, ln2g + l * Dc, ln2b + l * Dc, p_ln);

        // FF1 + gelu
        hgemm<EPI_GELU, false><<<dim3(FFc / 128, ROWSc / 128), 256>>>(
            p_ln, Dc, p_wff1T + (size_t)l * FFc * Dc, Dc,
            bff1 + l * FFc, (const float*)0, p_ff, FFc, Dc, 1.0f);

        // FF2 + residual
        hgemm<EPI_ADD, false><<<dim3(Dc / 128, ROWSc / 128), 256>>>(
            p_ff, FFc, p_wff2T + (size_t)l * Dc * FFc, FFc,
            bff2 + l * Dc, h, h, Dc, FFc, 1.0f);
    }
}

// round 5
// speedup vs baseline: 1.5454x; 1.5454x over previous
#include <cuda_runtime.h>
#include <cuda_fp16.h>
#include <math.h>
#include <stdint.h>

// ---------------------------------------------------------------------------
// SpatioTemporalPerformerEncoder — R5: fp16 mma + ldmatrix + coalesced feeds
// ---------------------------------------------------------------------------

#define Bc     2
#define Hc     8
#define Nc     4096
#define Dc     512
#define DHc    64
#define Mc     256
#define FFc    2048
#define DEPTHc 4
#define ROWSc  8192
#define BHc    16
#define QKVW   1536

#define DN_CONST    0.35355339059327373f
#define DIAG_SCALE  0.0625f
#define RATIO_CONST 0.0625f
#define EPSK        1e-4f
#define LNEPS       1e-5f

// ------------------------- scratch (device globals) ------------------------
__device__ float g_ln   [(size_t)ROWSc * Dc];
__device__ float g_qkv  [(size_t)ROWSc * QKVW];
__device__ float g_qp   [(size_t)BHc * Nc * Mc];
__device__ float g_kp   [(size_t)BHc * Nc * Mc];
__device__ float g_ff   [(size_t)ROWSc * FFc];
__device__ float g_ctx  [BHc * Mc * DHc];
__device__ float g_ksum [BHc * Mc];
__device__ float g_qdiag[BHc * Nc];
__device__ float g_kdiag[BHc * Nc];
__device__ float g_bmax [BHc * Nc];
__device__ float g_hmax [BHc];
__device__ float g_dinv [BHc * Nc];
// fp16 transposed weights [N][K] + fp16 proj
__device__ __half g_wqkvT[(size_t)DEPTHc * QKVW * Dc];
__device__ __half g_woT  [(size_t)DEPTHc * Dc * Dc];
__device__ __half g_wff1T[(size_t)DEPTHc * FFc * Dc];
__device__ __half g_wff2T[(size_t)DEPTHc * Dc * FFc];
__device__ __half g_projh[(size_t)DEPTHc * Mc * DHc];

// ------------------------------ helpers ------------------------------------
__device__ __forceinline__ uint32_t smem_to_u32(const void* p) {
    uint32_t a;
    asm("{ .reg .u64 t; cvta.to.shared.u64 t, %1; cvt.u32.u64 %0, t; }"
        : "=r"(a) : "l"(p));
    return a;
}
__device__ __forceinline__ uint32_t f2h2(float a, float b) {
    __half2 h = __floats2half2_rn(a, b);
    return *(uint32_t*)&h;
}
__device__ __forceinline__ void ldsm4(uint32_t& r0, uint32_t& r1, uint32_t& r2,
                                      uint32_t& r3, uint32_t a) {
    asm volatile("ldmatrix.sync.aligned.m8n8.x4.shared.b16 {%0,%1,%2,%3}, [%4];"
                 : "=r"(r0), "=r"(r1), "=r"(r2), "=r"(r3) : "r"(a));
}
__device__ __forceinline__ void ldsm2(uint32_t& r0, uint32_t& r1, uint32_t a) {
    asm volatile("ldmatrix.sync.aligned.m8n8.x2.shared.b16 {%0,%1}, [%2];"
                 : "=r"(r0), "=r"(r1) : "r"(a));
}
__device__ __forceinline__ void mma_f16(float c[4], const uint32_t a[4],
                                        const uint32_t b[2]) {
    asm volatile(
        "mma.sync.aligned.m16n8k16.row.col.f32.f16.f16.f32 "
        "{%0,%1,%2,%3}, {%4,%5,%6,%7}, {%8,%9}, {%0,%1,%2,%3};"
        : "+f"(c[0]), "+f"(c[1]), "+f"(c[2]), "+f"(c[3])
        : "r"(a[0]), "r"(a[1]), "r"(a[2]), "r"(a[3]), "r"(b[0]), "r"(b[1]));
}

// ------------------------- fp16 tensor-core GEMM ---------------------------
// C = scale*(A[M,K]fp32 @ Bh[N,K]fp16^T) (+bias)(+gelu|+residual)
// BM=BN=128, BK=32, 256 threads (8 warps 2x4), warp tile 64x32.
#define EPI_NONE 0
#define EPI_GELU 1
#define EPI_ADD  2

template <int EPI, bool BH>
__global__ __launch_bounds__(256)
void hgemm(const float* __restrict__ A, int lda,
           const __half* __restrict__ Bh, int ldb,
           const float* __restrict__ bias, const float* __restrict__ R,
           float* __restrict__ C, int ldc, int K, float scale) {
    __shared__ __align__(16) uint16_t sA[2][128 * 40];
    __shared__ __align__(16) uint16_t sB[2][128 * 40];

    if (BH) {
        int z = blockIdx.z;
        int b = z >> 3, h = z & 7;
        A += (size_t)b * Nc * lda + (size_t)h * DHc;
        C += (size_t)z * Nc * ldc;
    }
    int m0 = blockIdx.y * 128, n0 = blockIdx.x * 128;
    int tid = threadIdx.x, lane = tid & 31, warp = tid >> 5;
    int wm = warp >> 2, wn = warp & 3;

    // coalesced copy-in indexing
    int rowA = tid >> 3, cc = tid & 7;     // 8 thr/row, 32 rows/pass, 4 passes
    int rowB = tid >> 2, ccb = tid & 3;    // 4 thr/row, 64 rows/pass, 2 passes

    uint32_t aBase = smem_to_u32(sA), bBase = smem_to_u32(sB);
    uint32_t aOff = (((lane & 15) * 40) + (lane >> 4) * 8) * 2;
    uint32_t bOff = (((lane & 7) * 40) + ((lane >> 3) & 1) * 8) * 2;

    float c[4][4][4];
#pragma unroll
    for (int i = 0; i < 4; i++)
#pragma unroll
        for (int j = 0; j < 4; j++)
#pragma unroll
            for (int l = 0; l < 4; l++) c[i][j][l] = 0.0f;

    float4 raf[4];
    uint4 rbv[2];
#define PREF(t)                                                               \
    {                                                                         \
        int k0 = (t) * 32;                                                    \
        _Pragma("unroll")                                                     \
        for (int i = 0; i < 4; i++)                                           \
            raf[i] = *(const float4*)&A[(size_t)(m0 + rowA + i * 32) * lda +  \
                                        k0 + cc * 4];                         \
        _Pragma("unroll")                                                     \
        for (int i = 0; i < 2; i++)                                           \
            rbv[i] = *(const uint4*)&Bh[(size_t)(n0 + rowB + i * 64) * ldb +  \
                                        k0 + ccb * 8];                        \
    }
#define STORE(buf)                                                            \
    {                                                                         \
        _Pragma("unroll")                                                     \
        for (int i = 0; i < 4; i++) {                                         \
            uint2 u;                                                          \
            u.x = f2h2(raf[i].x, raf[i].y);                                   \
            u.y = f2h2(raf[i].z, raf[i].w);                                   \
            *(uint2*)&sA[buf][(rowA + i * 32) * 40 + cc * 4] = u;             \
        }                                                                     \
        _Pragma("unroll")                                                     \
        for (int i = 0; i < 2; i++)                                           \
            *(uint4*)&sB[buf][(rowB + i * 64) * 40 + ccb * 8] = rbv[i];       \
    }

    int T = K >> 5;
    PREF(0)
    STORE(0)
    __syncthreads();

    for (int t = 0; t < T; t++) {
        if (t + 1 < T) PREF(t + 1)
        int buf = t & 1;
        uint32_t aTile = aBase + buf * 10240;
        uint32_t bTile = bBase + buf * 10240;
#pragma unroll
        for (int k16 = 0; k16 < 32; k16 += 16) {
            uint32_t af[4][4], bf[4][2];
#pragma unroll
            for (int mi = 0; mi < 4; mi++)
                ldsm4(af[mi][0], af[mi][1], af[mi][2], af[mi][3],
                      aTile + ((wm * 64 + mi * 16) * 40 + k16) * 2 + aOff);
#pragma unroll
            for (int ni = 0; ni < 4; ni++)
                ldsm2(bf[ni][0], bf[ni][1],
                      bTile + ((wn * 32 + ni * 8) * 40 + k16) * 2 + bOff);
#pragma unroll
            for (int mi = 0; mi < 4; mi++)
#pragma unroll
                for (int ni = 0; ni < 4; ni++)
                    mma_f16(c[mi][ni], af[mi], bf[ni]);
        }
        if (t + 1 < T) STORE((t + 1) & 1)
        __syncthreads();
    }
#undef PREF
#undef STORE

    // epilogue
    int g = lane >> 2, tig = lane & 3;
#pragma unroll
    for (int mi = 0; mi < 4; mi++) {
#pragma unroll
        for (int ni = 0; ni < 4; ni++) {
            int row = m0 + wm * 64 + mi * 16 + g;
            int col = n0 + wn * 32 + ni * 8 + 2 * tig;
#pragma unroll
            for (int half = 0; half < 2; half++) {
                int r = row + half * 8;
                float v0 = c[mi][ni][half * 2 + 0] * scale;
                float v1 = c[mi][ni][half * 2 + 1] * scale;
                if (bias) { v0 += bias[col]; v1 += bias[col + 1]; }
                if (EPI == EPI_GELU) {
                    v0 = 0.5f * v0 * (1.0f + erff(v0 * 0.70710678118654752f));
                    v1 = 0.5f * v1 * (1.0f + erff(v1 * 0.70710678118654752f));
                }
                if (EPI == EPI_ADD) {
                    v0 += R[(size_t)r * ldc + col];
                    v1 += R[(size_t)r * ldc + col + 1];
                }
                float2 o = {v0, v1};
                *(float2*)&C[(size_t)r * ldc + col] = o;
            }
        }
    }
}

// --------------- batched weight transpose + convert to fp16 ----------------
// z in [0,16): weight transpose (type=z&3, layer=z>>2) fp32[K][N] -> fp16[N][K]
// z in [16,20): proj convert (layer=z-16) fp32 -> fp16, same layout
__global__ __launch_bounds__(256)
void transpose_all(const float* __restrict__ Wqkv, const float* __restrict__ Wo,
                   const float* __restrict__ Wff1, const float* __restrict__ Wff2,
                   const float* __restrict__ proj,
                   __half* __restrict__ qkvT, __half* __restrict__ woT,
                   __half* __restrict__ ff1T, __half* __restrict__ ff2T,
                   __half* __restrict__ projh) {
    __shared__ float tbuf[32][33];
    int z = blockIdx.z;
    if (z >= 16) {
        int l = z - 16;
        int idx = (blockIdx.y * gridDim.x + blockIdx.x) * 256 + threadIdx.x;
        if (idx < Mc * DHc)
            projh[(size_t)l * Mc * DHc + idx] =
                __float2half(proj[(size_t)l * Mc * DHc + idx]);
        return;
    }
    int type = z & 3, l = z >> 2;
    int K, N;
    const float* in;
    __half* out;
    if (type == 0)      { K = Dc;  N = QKVW; in = Wqkv + (size_t)l * Dc * QKVW; out = qkvT + (size_t)l * QKVW * Dc; }
    else if (type == 1) { K = Dc;  N = Dc;   in = Wo   + (size_t)l * Dc * Dc;   out = woT  + (size_t)l * Dc * Dc; }
    else if (type == 2) { K = Dc;  N = FFc;  in = Wff1 + (size_t)l * Dc * FFc;  out = ff1T + (size_t)l * FFc * Dc; }
    else                { K = FFc; N = Dc;   in = Wff2 + (size_t)l * FFc * Dc;  out = ff2T + (size_t)l * Dc * FFc; }

    int nx = blockIdx.x * 32, kx = blockIdx.y * 32;
    if (nx >= N || kx >= K) return;
    int tx = threadIdx.x & 31, ty = threadIdx.x >> 5;
#pragma unroll
    for (int i = 0; i < 4; i++)
        tbuf[ty + i * 8][tx] = in[(size_t)(kx + ty + i * 8) * N + nx + tx];
    __syncthreads();
#pragma unroll
    for (int i = 0; i < 4; i++)
        out[(size_t)(nx + ty + i * 8) * K + kx + tx] =
            __float2half(tbuf[tx][ty + i * 8]);
}

// ------------------------------ copy x -> h --------------------------------
__global__ void copy_kernel(const float* __restrict__ x, float* __restrict__ h) {
    size_t i = (size_t)blockIdx.x * 256 + threadIdx.x;
    h[i] = x[i];
}

// ------------------------------- layernorm ---------------------------------
__global__ __launch_bounds__(256)
void ln_kernel(const float* __restrict__ x, const float* __restrict__ g,
               const float* __restrict__ b, float* __restrict__ out) {
    int row = blockIdx.x;
    int t = threadIdx.x;
    const float* xr = x + (size_t)row * Dc;
    float v0 = xr[t], v1 = xr[t + 256];

    __shared__ float red[256];
    red[t] = v0 + v1;
    __syncthreads();
#pragma unroll
    for (int o = 128; o > 0; o >>= 1) {
        if (t < o) red[t] += red[t + o];
        __syncthreads();
    }
    float mu = red[0] * (1.0f / Dc);
    __syncthreads();

    float d0 = v0 - mu, d1 = v1 - mu;
    red[t] = d0 * d0 + d1 * d1;
    __syncthreads();
#pragma unroll
    for (int o = 128; o > 0; o >>= 1) {
        if (t < o) red[t] += red[t + o];
        __syncthreads();
    }
    float rs = rsqrtf(red[0] * (1.0f / Dc) + LNEPS);

    float* orow = out + (size_t)row * Dc;
    orow[t]       = d0 * rs * g[t]       + b[t];
    orow[t + 256] = d1 * rs * g[t + 256] + b[t + 256];
}

// ------------------- diag: per-(bh,row) 0.5*dn^2*|q|^2, |k|^2 --------------
__global__ __launch_bounds__(256)
void diag_kernel(const float* __restrict__ qkv, float* __restrict__ qdiag,
                 float* __restrict__ kdiag) {
    int row = blockIdx.x;
    int w = threadIdx.x >> 5, lane = threadIdx.x & 31;
    const float* base = qkv + (size_t)row * QKVW + w * DHc;
    float q0 = base[lane], q1 = base[lane + 32];
    float k0 = base[Dc + lane], k1 = base[Dc + lane + 32];
    float sq = q0 * q0 + q1 * q1;
    float sk = k0 * k0 + k1 * k1;
#pragma unroll
    for (int o = 16; o > 0; o >>= 1) {
        sq += __shfl_down_sync(0xffffffffu, sq, o);
        sk += __shfl_down_sync(0xffffffffu, sk, o);
    }
    if (lane == 0) {
        int bh = (row >> 12) * Hc + w;
        int n = row & (Nc - 1);
        qdiag[(size_t)bh * Nc + n] = sq * DIAG_SCALE;
        kdiag[(size_t)bh * Nc + n] = sk * DIAG_SCALE;
    }
}

// ---------------- q features: per-row max + exp (in place) -----------------
__global__ __launch_bounds__(256)
void featq_finish(float* __restrict__ qp, const float* __restrict__ qdiag) {
    int w = threadIdx.x >> 5, lane = threadIdx.x & 31;
    int rr = blockIdx.x * 8 + w;
    float* p = qp + (size_t)rr * Mc + lane * 8;
    float4 v0 = *(float4*)p;
    float4 v1 = *(float4*)(p + 4);
    float mx = fmaxf(fmaxf(fmaxf(v0.x, v0.y), fmaxf(v0.z, v0.w)),
                     fmaxf(fmaxf(v1.x, v1.y), fmaxf(v1.z, v1.w)));
#pragma unroll
    for (int o = 16; o > 0; o >>= 1)
        mx = fmaxf(mx, __shfl_xor_sync(0xffffffffu, mx, o));
    float sub = qdiag[rr] + mx;
    v0.x = RATIO_CONST * (expf(v0.x - sub) + EPSK);
    v0.y = RATIO_CONST * (expf(v0.y - sub) + EPSK);
    v0.z = RATIO_CONST * (expf(v0.z - sub) + EPSK);
    v0.w = RATIO_CONST * (expf(v0.w - sub) + EPSK);
    v1.x = RATIO_CONST * (expf(v1.x - sub) + EPSK);
    v1.y = RATIO_CONST * (expf(v1.y - sub) + EPSK);
    v1.z = RATIO_CONST * (expf(v1.z - sub) + EPSK);
    v1.w = RATIO_CONST * (expf(v1.w - sub) + EPSK);
    *(float4*)p = v0;
    *(float4*)(p + 4) = v1;
}

// ---------------- k features pass A: per-row max ---------------------------
__global__ __launch_bounds__(256)
void featk_rowmax(const float* __restrict__ kp, float* __restrict__ bmax) {
    int w = threadIdx.x >> 5, lane = threadIdx.x & 31;
    int rr = blockIdx.x * 8 + w;
    const float* p = kp + (size_t)rr * Mc + lane * 8;
    float4 v0 = *(const float4*)p;
    float4 v1 = *(const float4*)(p + 4);
    float mx = fmaxf(fmaxf(fmaxf(v0.x, v0.y), fmaxf(v0.z, v0.w)),
                     fmaxf(fmaxf(v1.x, v1.y), fmaxf(v1.z, v1.w)));
#pragma unroll
    for (int o = 16; o > 0; o >>= 1)
        mx = fmaxf(mx, __shfl_xor_sync(0xffffffffu, mx, o));
    if (lane == 0) bmax[rr] = mx;
}

// ------------------------- per-head global max -----------------------------
__global__ __launch_bounds__(256)
void hmax_kernel(const float* __restrict__ bmax, float* __restrict__ hmax) {
    int bh = blockIdx.x;
    int t = threadIdx.x;
    float m = -1e30f;
    for (int i = t; i < Nc; i += 256) m = fmaxf(m, bmax[(size_t)bh * Nc + i]);
#pragma unroll
    for (int o = 16; o > 0; o >>= 1) m = fmaxf(m, __shfl_xor_sync(0xffffffffu, m, o));
    __shared__ float w[8];
    if ((t & 31) == 0) w[t >> 5] = m;
    __syncthreads();
    if (t == 0) {
        float mm = w[0];
#pragma unroll
        for (int i = 1; i < 8; i++) mm = fmaxf(mm, w[i]);
        hmax[bh] = mm;
    }
}

// ---------------- k features pass B: exp (in place) ------------------------
__global__ __launch_bounds__(256)
void featk2_kernel(float* __restrict__ kp, const float* __restrict__ kdiag,
                   const float* __restrict__ hmax) {
    size_t i4 = (size_t)blockIdx.x * 256 + threadIdx.x;
    size_t idx = i4 * 4;
    int bh = (int)(idx >> 20);
    int n  = (int)((idx >> 8) & (Nc - 1));
    float sub = kdiag[(size_t)bh * Nc + n] + hmax[bh];
    float4 v = *(float4*)&kp[idx];
    v.x = RATIO_CONST * (expf(v.x - sub) + EPSK);
    v.y = RATIO_CONST * (expf(v.y - sub) + EPSK);
    v.z = RATIO_CONST * (expf(v.z - sub) + EPSK);
    v.w = RATIO_CONST * (expf(v.w - sub) + EPSK);
    *(float4*)&kp[idx] = v;
}

// ---------------------------- zero ctx / ksum ------------------------------
__global__ void zero_kernel(float* __restrict__ ctx, float* __restrict__ ksum) {
    int i = blockIdx.x * 256 + threadIdx.x;
    if (i < BHc * Mc * DHc) ctx[i] = 0.0f;
    if (i < BHc * Mc) ksum[i] = 0.0f;
}

// --------------------------------- k_sum -----------------------------------
__global__ __launch_bounds__(256)
void ksum_kernel(const float* __restrict__ kp, float* __restrict__ ksum) {
    int bh = blockIdx.x;
    int n0 = blockIdx.y * (Nc / 8);
    int t = threadIdx.x;
    float s = 0.0f;
    const float* base = kp + ((size_t)bh * Nc + n0) * Mc + t;
    for (int n = 0; n < Nc / 8; n++) s += base[(size_t)n * Mc];
    atomicAdd(&ksum[bh * Mc + t], s);
}

// ------------------------------- ctx = kp^T v ------------------------------
__global__ __launch_bounds__(256)
void ctx_kernel(const float* __restrict__ kp, const float* __restrict__ qkv,
                float* __restrict__ ctx) {
    int bh = blockIdx.x;
    int split = blockIdx.y;
    int b = bh >> 3, h = bh & 7;
    const int NS = Nc / 16;
    int n0 = split * NS;
    int t = threadIdx.x;
    int tx = t & 63;
    int ty = t >> 6;

    __shared__ float kps[32][256];
    __shared__ float vs[32][64];

    float acc[4][16];
#pragma unroll
    for (int i = 0; i < 4; i++)
#pragma unroll
        for (int j = 0; j < 16; j++) acc[i][j] = 0.0f;

    for (int nc = 0; nc < NS; nc += 32) {
#pragma unroll
        for (int i = 0; i < 8; i++) {
            int li = t + i * 256;
            int r = li >> 6;
            int cc = (li & 63) * 4;
            *(float4*)&kps[r][cc] =
                *(const float4*)&kp[((size_t)bh * Nc + n0 + nc + r) * Mc + cc];
        }
#pragma unroll
        for (int i = 0; i < 2; i++) {
            int li = t + i * 256;
            int r = li >> 4;
            int cc = (li & 15) * 4;
            *(float4*)&vs[r][cc] =
                *(const float4*)&qkv[((size_t)(b * Nc + n0 + nc + r)) * QKVW +
                                     2 * Dc + h * DHc + cc];
        }
        __syncthreads();

#pragma unroll 4
        for (int nn = 0; nn < 32; nn++) {
            float kv[4];
#pragma unroll
            for (int mm = 0; mm < 4; mm++) kv[mm] = kps[nn][tx + mm * 64];
            float vv[16];
            *(float4*)&vv[0]  = *(float4*)&vs[nn][ty * 16];
            *(float4*)&vv[4]  = *(float4*)&vs[nn][ty * 16 + 4];
            *(float4*)&vv[8]  = *(float4*)&vs[nn][ty * 16 + 8];
            *(float4*)&vv[12] = *(float4*)&vs[nn][ty * 16 + 12];
#pragma unroll
            for (int mm = 0; mm < 4; mm++)
#pragma unroll
                for (int dd = 0; dd < 16; dd++)
                    acc[mm][dd] = fmaf(kv[mm], vv[dd], acc[mm][dd]);
        }
        __syncthreads();
    }

#pragma unroll
    for (int mm = 0; mm < 4; mm++)
#pragma unroll
        for (int dd = 0; dd < 16; dd++)
            atomicAdd(&ctx[((size_t)bh * Mc + tx + mm * 64) * DHc + ty * 16 + dd],
                      acc[mm][dd]);
}

// ------------------------------- d_inv -------------------------------------
__global__ __launch_bounds__(256)
void dinv_kernel(const float* __restrict__ qp, const float* __restrict__ ksum,
                 float* __restrict__ dinv) {
    int w = threadIdx.x >> 5, lane = threadIdx.x & 31;
    int rr = blockIdx.x * 8 + w;
    int bh = rr >> 12;
    float s = 0.0f;
#pragma unroll
    for (int j = 0; j < 8; j++) {
        int m = lane + j * 32;
        s += qp[(size_t)rr * Mc + m] * ksum[bh * Mc + m];
    }
#pragma unroll
    for (int o = 16; o > 0; o >>= 1) s += __shfl_down_sync(0xffffffffu, s, o);
    if (lane == 0) dinv[rr] = 1.0f / s;
}

// ---------------------- out = dinv * (qp @ ctx), merge heads ---------------
__global__ __launch_bounds__(256)
void attnout_kernel(const float* __restrict__ qp, const float* __restrict__ ctx,
                    const float* __restrict__ dinv, float* __restrict__ out) {
    int bh = blockIdx.y;
    int n0 = blockIdx.x * 64;
    int b = bh >> 3, h = bh & 7;
    int t = threadIdx.x;
    int tx = t & 15, ty = t >> 4;

    __shared__ float qs[64][36];
    __shared__ float cs[32][64];

    float acc[4][4];
#pragma unroll
    for (int i = 0; i < 4; i++)
#pragma unroll
        for (int j = 0; j < 4; j++) acc[i][j] = 0.0f;

    for (int k0 = 0; k0 < Mc; k0 += 32) {
#pragma unroll
        for (int i = 0; i < 2; i++) {
            int l = t + i * 256;
            int r = l >> 3;
            int cc = (l & 7) * 4;
            *(float4*)&qs[r][cc] =
                *(const float4*)&qp[((size_t)bh * Nc + n0 + r) * Mc + k0 + cc];
        }
#pragma unroll
        for (int i = 0; i < 2; i++) {
            int l = t + i * 256;
            int r = l >> 4;
            int cc = (l & 15) * 4;
            *(float4*)&cs[r][cc] =
                *(const float4*)&ctx[((size_t)bh * Mc + k0 + r) * DHc + cc];
        }
        __syncthreads();

#pragma unroll
        for (int k = 0; k < 32; k++) {
            float a[4];
#pragma unroll
            for (int i = 0; i < 4; i++) a[i] = qs[ty * 4 + i][k];
            float bb[4];
            *(float4*)bb = *(float4*)&cs[k][tx * 4];
#pragma unroll
            for (int i = 0; i < 4; i++)
#pragma unroll
                for (int j = 0; j < 4; j++)
                    acc[i][j] = fmaf(a[i], bb[j], acc[i][j]);
        }
        __syncthreads();
    }

#pragma unroll
    for (int i = 0; i < 4; i++) {
        int n = n0 + ty * 4 + i;
        float di = dinv[(size_t)bh * Nc + n];
#pragma unroll
        for (int j = 0; j < 4; j++)
            out[((size_t)(b * Nc + n)) * Dc + h * DHc + tx * 4 + j] = acc[i][j] * di;
    }
}

// ------------------------------- launch ------------------------------------
extern "C" void kernel_launch(void* const* d_in, const int* in_sizes, int n_in,
                              void* d_out, int out_size) {
    (void)in_sizes; (void)n_in; (void)out_size;
    const float* x    = (const float*)d_in[0];
    const float* proj = (const float*)d_in[1];
    const float* ln1g = (const float*)d_in[2];
    const float* ln1b = (const float*)d_in[3];
    const float* Wqkv = (const float*)d_in[4];
    const float* bqkv = (const float*)d_in[5];
    const float* Wo   = (const float*)d_in[6];
    const float* bo   = (const float*)d_in[7];
    const float* ln2g = (const float*)d_in[8];
    const float* ln2b = (const float*)d_in[9];
    const float* Wff1 = (const float*)d_in[10];
    const float* bff1 = (const float*)d_in[11];
    const float* Wff2 = (const float*)d_in[12];
    const float* bff2 = (const float*)d_in[13];
    float* h = (float*)d_out;

    static float *p_ln = 0, *p_qkv = 0, *p_qp = 0, *p_kp = 0, *p_ff = 0,
                 *p_ctx = 0, *p_ksum = 0, *p_qdiag = 0, *p_kdiag = 0,
                 *p_bmax = 0, *p_hmax = 0, *p_dinv = 0;
    static __half *p_wqkvT = 0, *p_woT = 0, *p_wff1T = 0, *p_wff2T = 0,
                  *p_projh = 0;
    if (!p_ln) {
        cudaGetSymbolAddress((void**)&p_ln, g_ln);
        cudaGetSymbolAddress((void**)&p_qkv, g_qkv);
        cudaGetSymbolAddress((void**)&p_qp, g_qp);
        cudaGetSymbolAddress((void**)&p_kp, g_kp);
        cudaGetSymbolAddress((void**)&p_ff, g_ff);
        cudaGetSymbolAddress((void**)&p_ctx, g_ctx);
        cudaGetSymbolAddress((void**)&p_ksum, g_ksum);
        cudaGetSymbolAddress((void**)&p_qdiag, g_qdiag);
        cudaGetSymbolAddress((void**)&p_kdiag, g_kdiag);
        cudaGetSymbolAddress((void**)&p_bmax, g_bmax);
        cudaGetSymbolAddress((void**)&p_hmax, g_hmax);
        cudaGetSymbolAddress((void**)&p_dinv, g_dinv);
        cudaGetSymbolAddress((void**)&p_wqkvT, g_wqkvT);
        cudaGetSymbolAddress((void**)&p_woT, g_woT);
        cudaGetSymbolAddress((void**)&p_wff1T, g_wff1T);
        cudaGetSymbolAddress((void**)&p_wff2T, g_wff2T);
        cudaGetSymbolAddress((void**)&p_projh, g_projh);
    }

    // launch 0: weight transposes + fp16 conversion (incl. proj)
    transpose_all<<<dim3(64, 64, 20), 256>>>(Wqkv, Wo, Wff1, Wff2, proj,
                                             p_wqkvT, p_woT, p_wff1T, p_wff2T,
                                             p_projh);
    // launch 1
    copy_kernel<<<(ROWSc * Dc) / 256, 256>>>(x, h);

    for (int l = 0; l < DEPTHc; l++) {
        const __half* pjh = p_projh + (size_t)l * Mc * DHc;

        ln_kernel<<<ROWSc, 256>>>(h, ln1g + l * Dc, ln1b + l * Dc, p_ln);  // 2

        // launch 3 (profiled): QKV
        hgemm<EPI_NONE, false><<<dim3(QKVW / 128, ROWSc / 128), 256>>>(
            p_ln, Dc, p_wqkvT + (size_t)l * QKVW * Dc, Dc,
            bqkv + l * QKVW, (const float*)0, p_qkv, QKVW, Dc, 1.0f);

        zero_kernel<<<(BHc * Mc * DHc + 255) / 256, 256>>>(p_ctx, p_ksum);

        // dd_q / dd_k
        hgemm<EPI_NONE, true><<<dim3(Mc / 128, Nc / 128, BHc), 256>>>(
            p_qkv, QKVW, pjh, DHc, (const float*)0, (const float*)0,
            p_qp, Mc, DHc, DN_CONST);
        hgemm<EPI_NONE, true><<<dim3(Mc / 128, Nc / 128, BHc), 256>>>(
            p_qkv + Dc, QKVW, pjh, DHc, (const float*)0, (const float*)0,
            p_kp, Mc, DHc, DN_CONST);

        diag_kernel<<<ROWSc, 256>>>(p_qkv, p_qdiag, p_kdiag);
        featq_finish<<<(BHc * Nc) / 8, 256>>>(p_qp, p_qdiag);
        featk_rowmax<<<(BHc * Nc) / 8, 256>>>(p_kp, p_bmax);
        hmax_kernel<<<BHc, 256>>>(p_bmax, p_hmax);
        featk2_kernel<<<(BHc * Nc * Mc / 4) / 256, 256>>>(p_kp, p_kdiag, p_hmax);

        ksum_kernel<<<dim3(BHc, 8), 256>>>(p_kp, p_ksum);
        ctx_kernel<<<dim3(BHc, 16), 256>>>(p_kp, p_qkv, p_ctx);
        dinv_kernel<<<(BHc * Nc) / 8, 256>>>(p_qp, p_ksum, p_dinv);
        attnout_kernel<<<dim3(Nc / 64, BHc), 256>>>(p_qp, p_ctx, p_dinv, p_ln);

        // Wo + residual
        hgemm<EPI_ADD, false><<<dim3(Dc / 128, ROWSc / 128), 256>>>(
            p_ln, Dc, p_woT + (size_t)l * Dc * Dc, Dc,
            bo + l * Dc, h, h, Dc, Dc, 1.0f);

        ln_kernel<<<ROWSc, 256>>>(h, ln2g + l * Dc, ln2b + l * Dc, p_ln);

        // FF1 + gelu
        hgemm<EPI_GELU, false><<<dim3(FFc / 128, ROWSc / 128), 256>>>(
            p_ln, Dc, p_wff1T + (size_t)l * FFc * Dc, Dc,
            bff1 + l * FFc, (const float*)0, p_ff, FFc, Dc, 1.0f);

        // FF2 + residual
        hgemm<EPI_ADD, false><<<dim3(Dc / 128, ROWSc / 128), 256>>>(
            p_ff, FFc, p_wff2T + (size_t)l * Dc * FFc, FFc,
            bff2 + l * Dc, h, h, Dc, FFc, 1.0f);
    }
}